// round 9
// baseline (speedup 1.0000x reference)
#include <cuda_runtime.h>

// Sobel edge magnitude + channel mean.
// x: [B=16, C=64, H=256, W=256] f32 -> out: [B,1,H,W] f32
//
// Separable: p_i = x[i][w+1]-x[i][w-1], q_i = x[i][w-1]+2x[i][w]+x[i][w+1]
//   gx(r) = p_r + 2 p_{r+1} + p_{r+2},   gy(r) = q_{r+2} - q_r
//
// R9 changes vs R8:
//  - Register double-buffer software pipeline over the channel loop: issue
//    channel k+1's 18 loads BEFORE computing channel k. Loads stay in flight
//    continuously (prefetch distance ~ a full compute phase), removing the
//    long-scoreboard stall on first consume. 2 CTAs/SM (~118 regs).

#define BB 16
#define CC 64
#define HH 256
#define WW 256
#define RR 4          // output rows per tile
#define NROWS (RR + 2)
#define NWARPS 8      // warps per block (channel stride)
#define TW 128        // columns per warp tile (32 lanes * 4)
#define HSTRIPS (HH / RR)
#define KITERS (CC / NWARPS)

typedef unsigned long long u64;

__device__ __forceinline__ float sqrt_approx(float v) {
    float y;
    asm("sqrt.approx.f32 %0, %1;" : "=f"(y) : "f"(v));
    return y;
}
__device__ __forceinline__ u64 pk(float lo, float hi) {
    u64 r; asm("mov.b64 %0, {%1, %2};" : "=l"(r) : "f"(lo), "f"(hi)); return r;
}
__device__ __forceinline__ void upk(float& lo, float& hi, u64 v) {
    asm("mov.b64 {%0, %1}, %2;" : "=f"(lo), "=f"(hi) : "l"(v));
}
__device__ __forceinline__ u64 add2(u64 a, u64 b) {
    u64 r; asm("add.rn.f32x2 %0, %1, %2;" : "=l"(r) : "l"(a), "l"(b)); return r;
}
__device__ __forceinline__ u64 fma2(u64 a, u64 b, u64 c) {
    u64 r; asm("fma.rn.f32x2 %0, %1, %2, %3;" : "=l"(r) : "l"(a), "l"(b), "l"(c)); return r;
}

struct RowBuf {
    u64  cl[NROWS];   // (v0, v1) per row
    u64  ch[NROWS];   // (v2, v3) per row
    float lf[NROWS];
    float rg[NROWS];
};

__device__ __forceinline__ void load_strip(
    RowBuf& buf, const float* __restrict__ plane,
    int gh0, int gw4, bool top_oob, bool bot_oob,
    bool has_left, bool has_right)
{
#pragma unroll
    for (int i = 0; i < NROWS; i++) {
        const int gh = gh0 - 1 + i;
        const bool oob = (i == 0 && top_oob) || (i == NROWS - 1 && bot_oob);
        const float* __restrict__ row = plane + gh * WW;
        if (oob) {
            buf.cl[i] = 0; buf.ch[i] = 0;
            buf.lf[i] = 0.f; buf.rg[i] = 0.f;
        } else {
            const ulonglong2 vv = *reinterpret_cast<const ulonglong2*>(row + gw4);
            buf.cl[i] = vv.x;
            buf.ch[i] = vv.y;
            buf.lf[i] = has_left  ? row[gw4 - 1] : 0.f;
            buf.rg[i] = has_right ? row[gw4 + 4] : 0.f;
        }
    }
}

__device__ __forceinline__ void compute_strip(
    const RowBuf& buf, float4* acc,
    u64 TWO2, u64 NEG1, u64 EPS2)
{
    u64 p0l = 0, p0h = 0, p1l = 0, p1h = 0;
    u64 q0l = 0, q0h = 0, q1l = 0, q1h = 0;
#pragma unroll
    for (int i = 0; i < NROWS; i++) {
        const u64 cl = buf.cl[i];
        const u64 ch = buf.ch[i];
        float v0, v1, v2, v3;
        upk(v0, v1, cl);
        upk(v2, v3, ch);
        const u64 ll = pk(buf.lf[i], v0);
        const u64 lh = pk(v1, v2);
        const u64 rh = pk(v3, buf.rg[i]);

        const u64 pl = fma2(NEG1, ll, lh);            // r - l
        const u64 ph = fma2(NEG1, lh, rh);
        const u64 ql = add2(fma2(cl, TWO2, ll), lh);  // l + 2c + r
        const u64 qh = add2(fma2(ch, TWO2, lh), rh);

        if (i >= 2) {
            const int r = i - 2;
            const u64 gxl = add2(fma2(p1l, TWO2, p0l), pl);
            const u64 gxh = add2(fma2(p1h, TWO2, p0h), ph);
            const u64 gyl = fma2(NEG1, q0l, ql);
            const u64 gyh = fma2(NEG1, q0h, qh);
            const u64 m_l = fma2(gxl, gxl, fma2(gyl, gyl, EPS2));
            const u64 m_h = fma2(gxh, gxh, fma2(gyh, gyh, EPS2));
            float m0, m1, m2, m3;
            upk(m0, m1, m_l);
            upk(m2, m3, m_h);
            acc[r].x += sqrt_approx(m0);
            acc[r].y += sqrt_approx(m1);
            acc[r].z += sqrt_approx(m2);
            acc[r].w += sqrt_approx(m3);
        }
        p0l = p1l; p0h = p1h; p1l = pl; p1h = ph;
        q0l = q1l; q0h = q1h; q1l = ql; q1h = qh;
    }
}

__global__ __launch_bounds__(256, 2)
void sobel_mean_kernel(const float* __restrict__ x, float* __restrict__ out) {
    const int wq   = blockIdx.x;   // column tile: 0..1
    const int hs   = blockIdx.y;   // row strip:   0..63
    const int b    = blockIdx.z;
    const int tid  = threadIdx.x;
    const int wid  = tid >> 5;
    const int lane = tid & 31;

    const int gw4 = wq * TW + lane * 4;
    const int gh0 = hs * RR;

    const bool top_oob = (hs == 0);
    const bool bot_oob = (hs == HSTRIPS - 1);
    const bool has_left  = (gw4 != 0);
    const bool has_right = (gw4 + 4 != WW);

    __shared__ float s_acc[NWARPS][RR * TW];   // 16 KB

    const u64 TWO2 = pk(2.0f, 2.0f);
    const u64 NEG1 = pk(-1.0f, -1.0f);
    const u64 EPS2 = pk(1e-12f, 1e-12f);

    float4 acc[RR];
#pragma unroll
    for (int r = 0; r < RR; r++) acc[r] = make_float4(0.f, 0.f, 0.f, 0.f);

    const float* __restrict__ plane0 =
        x + ((size_t)(b * CC + wid)) * (HH * WW);
    const size_t cstride = (size_t)NWARPS * (HH * WW);

    RowBuf buf0, buf1;

    // Prologue: load k=0 into buf0.
    load_strip(buf0, plane0, gh0, gw4, top_oob, bot_oob, has_left, has_right);

    // Pipelined main loop, unrolled x2 so buffer roles are static.
#pragma unroll 1
    for (int k = 0; k < KITERS; k += 2) {
        // prefetch k+1 (always valid: k+1 <= KITERS-1 for even k < KITERS)
        load_strip(buf1, plane0 + (size_t)(k + 1) * cstride,
                   gh0, gw4, top_oob, bot_oob, has_left, has_right);
        compute_strip(buf0, acc, TWO2, NEG1, EPS2);

        if (k + 2 < KITERS) {
            load_strip(buf0, plane0 + (size_t)(k + 2) * cstride,
                       gh0, gw4, top_oob, bot_oob, has_left, has_right);
        }
        compute_strip(buf1, acc, TWO2, NEG1, EPS2);
    }

    // Stage per-warp partials, then block-reduce across the 8 warps.
#pragma unroll
    for (int r = 0; r < RR; r++)
        *reinterpret_cast<float4*>(&s_acc[wid][r * TW + lane * 4]) = acc[r];
    __syncthreads();

    const float inv = 1.0f / (float)CC;
#pragma unroll
    for (int j = 0; j < (RR * TW) / 256; j++) {
        const int px = tid + 256 * j;          // 0..511
        float s = 0.f;
#pragma unroll
        for (int w = 0; w < NWARPS; w++) s += s_acc[w][px];
        const int r   = px / TW;
        const int col = px % TW;
        out[((size_t)b * HH + (gh0 + r)) * WW + wq * TW + col] = s * inv;
    }
}

extern "C" void kernel_launch(void* const* d_in, const int* in_sizes, int n_in,
                              void* d_out, int out_size) {
    const float* x = (const float*)d_in[0];
    float* out = (float*)d_out;
    dim3 grid(WW / TW, HSTRIPS, BB);   // (2, 64, 16) = 2048 blocks
    sobel_mean_kernel<<<grid, 256>>>(x, out);
}